// round 4
// baseline (speedup 1.0000x reference)
#include <cuda_runtime.h>
#include <cuda_bf16.h>
#include <cstdint>

#define NB   256
#define LAT  20
#define HID  128
#define NG   25000
#define NGB  1000
#define NC   7

// output tuple (mu, theta, pi_drop, sample, pi) concatenated, fp32
#define OFF_MU      0
#define OFF_THETA   6400000
#define OFF_PD      12800000
#define OFF_SAMPLE  19200000
#define OFF_PI      25600000

// scratch (device globals; no allocations allowed)
__device__ __align__(16) float g_x [NB * HID];   // x[b][h]
__device__ __align__(16) float g_xt[HID * NB];   // x^T[h][b]
__device__ __align__(16) float g_p [NB * NGB * NC];  // softmax(rho) as [b][o][c]
__device__ __align__(16) float g_lp[NB * NGB * NC];  // log(p + 1e-20)

// ---------------------------------------------------------------------------
// K1: x = relu(bn(relu(bn(z@w0+b0)) @ w1 + b1)), write both layouts
// ---------------------------------------------------------------------------
__global__ __launch_bounds__(HID) void k_mlp(
    const float* __restrict__ z,  const float* __restrict__ w0,
    const float* __restrict__ b0, const float* __restrict__ g0,
    const float* __restrict__ be0,const float* __restrict__ m0,
    const float* __restrict__ v0,
    const float* __restrict__ w1, const float* __restrict__ b1,
    const float* __restrict__ g1, const float* __restrict__ be1,
    const float* __restrict__ m1, const float* __restrict__ v1) {
  __shared__ float zs[LAT];
  __shared__ float xs[HID];
  const int b = blockIdx.x;
  const int h = threadIdx.x;
  if (h < LAT) zs[h] = z[b * LAT + h];
  __syncthreads();
  float acc = b0[h];
#pragma unroll
  for (int k = 0; k < LAT; k++) acc = fmaf(zs[k], w0[k * HID + h], acc);
  acc = (acc - m0[h]) * rsqrtf(v0[h] + 1e-3f) * g0[h] + be0[h];
  acc = fmaxf(acc, 0.0f);
  xs[h] = acc;
  __syncthreads();
  float a2 = b1[h];
#pragma unroll
  for (int k = 0; k < HID; k++) a2 = fmaf(xs[k], w1[k * HID + h], a2);
  a2 = (a2 - m1[h]) * rsqrtf(v1[h] + 1e-3f) * g1[h] + be1[h];
  a2 = fmaxf(a2, 0.0f);
  g_x[b * HID + h]  = a2;
  g_xt[h * NB + b]  = a2;
}

// ---------------------------------------------------------------------------
// K2: theta = exp(x@wr+br), pi_drop = x@wd+bd
// 64(batch) x 64(gene) tile, BK=32, 256 threads, 4x4 micro-tile per output
// ---------------------------------------------------------------------------
__global__ __launch_bounds__(256) void k_gemm(
    const float* __restrict__ wr, const float* __restrict__ br,
    const float* __restrict__ wd, const float* __restrict__ bd,
    float* __restrict__ out) {
  __shared__ float xs[32][68];   // [k][m], pad 68 keeps float4 16B-aligned
  __shared__ float wrs[32][64];  // [k][g]
  __shared__ float wds[32][64];
  const int tid = threadIdx.x;
  const int tx = tid & 15, ty = tid >> 4;
  const int g0 = blockIdx.x * 64;
  const int m0 = blockIdx.y * 64;
  float aT[4][4] = {}, aD[4][4] = {};

  for (int kc = 0; kc < HID; kc += 32) {
    const int c = tid & 31, r0 = tid >> 5;
#pragma unroll
    for (int t = 0; t < 8; t++) {
      const int r = r0 + t * 8;
      xs[c][r] = g_x[(m0 + r) * HID + kc + c];
    }
    const int j = tid & 63, kk0 = tid >> 6;
#pragma unroll
    for (int t = 0; t < 8; t++) {
      const int kk = kk0 + t * 4;
      const int g = g0 + j;
      const bool ok = (g < NG);
      wrs[kk][j] = ok ? wr[(kc + kk) * NG + g] : 0.0f;
      wds[kk][j] = ok ? wd[(kc + kk) * NG + g] : 0.0f;
    }
    __syncthreads();
#pragma unroll
    for (int k = 0; k < 32; k++) {
      const float4 av  = *(const float4*)&xs[k][ty * 4];
      const float4 brv = *(const float4*)&wrs[k][tx * 4];
      const float4 bdv = *(const float4*)&wds[k][tx * 4];
      const float a[4]  = {av.x, av.y, av.z, av.w};
      const float wrv4[4] = {brv.x, brv.y, brv.z, brv.w};
      const float wdv4[4] = {bdv.x, bdv.y, bdv.z, bdv.w};
#pragma unroll
      for (int i = 0; i < 4; i++)
#pragma unroll
        for (int jj = 0; jj < 4; jj++) {
          aT[i][jj] = fmaf(a[i], wrv4[jj], aT[i][jj]);
          aD[i][jj] = fmaf(a[i], wdv4[jj], aD[i][jj]);
        }
    }
    __syncthreads();
  }
#pragma unroll
  for (int jj = 0; jj < 4; jj++) {
    const int g = g0 + tx * 4 + jj;
    if (g >= NG) continue;
    const float brv = br[g], bdv = bd[g];
#pragma unroll
    for (int i = 0; i < 4; i++) {
      const int mrow = m0 + ty * 4 + i;
      const size_t idx = (size_t)mrow * NG + g;
      out[OFF_THETA + idx] = expf(aT[i][jj] + brv);
      out[OFF_PD + idx]    = aD[i][jj] + bdv;
    }
  }
}

// ---------------------------------------------------------------------------
// K3: rho[c][b][o] = x@wrho[c] + brho[c]; softmax over c; store p and log(p+eps)
// 125 blocks x 8 o-cols each, 256 threads = batch dim, acc[7][8] in regs
// ---------------------------------------------------------------------------
__global__ __launch_bounds__(256) void k_rho(
    const float* __restrict__ wrho, const float* __restrict__ brho) {
  __shared__ float ws[NC * HID * 8];  // [c][h][j] contiguous = 28 KB
  const int tid = threadIdx.x;
  const int b = tid;
  const int o0 = blockIdx.x * 8;
  for (int idx = tid; idx < NC * HID * 8; idx += 256) {
    const int c = idx >> 10;
    const int rem = idx & 1023;
    const int h = rem >> 3, j = rem & 7;
    ws[idx] = wrho[c * HID * NGB + h * NGB + o0 + j];
  }
  __syncthreads();

  float acc[NC][8] = {};
  for (int h = 0; h < HID; h++) {
    const float xv = g_xt[h * NB + b];
#pragma unroll
    for (int c = 0; c < NC; c++) {
      const float4* wp = (const float4*)&ws[(c * HID + h) * 8];
      const float4 w0 = wp[0], w1 = wp[1];
      acc[c][0] = fmaf(xv, w0.x, acc[c][0]);
      acc[c][1] = fmaf(xv, w0.y, acc[c][1]);
      acc[c][2] = fmaf(xv, w0.z, acc[c][2]);
      acc[c][3] = fmaf(xv, w0.w, acc[c][3]);
      acc[c][4] = fmaf(xv, w1.x, acc[c][4]);
      acc[c][5] = fmaf(xv, w1.y, acc[c][5]);
      acc[c][6] = fmaf(xv, w1.z, acc[c][6]);
      acc[c][7] = fmaf(xv, w1.w, acc[c][7]);
    }
  }
#pragma unroll
  for (int j = 0; j < 8; j++) {
    float v[NC];
    float m = -3.0e38f;
#pragma unroll
    for (int c = 0; c < NC; c++) {
      v[c] = acc[c][j] + brho[c * NGB + o0 + j];
      m = fmaxf(m, v[c]);
    }
    float e[NC], sum = 0.0f;
#pragma unroll
    for (int c = 0; c < NC; c++) { e[c] = expf(v[c] - m); sum += e[c]; }
    const int base = (b * NGB + o0 + j) * NC;
#pragma unroll
    for (int c = 0; c < NC; c++) {
      const float p = e[c] / sum;
      g_p[base + c]  = p;
      g_lp[base + c] = logf(p + 1e-20f);
    }
  }
}

// ---------------------------------------------------------------------------
// K4: Gumbel-softmax straight-through sampler + mu + pi output
// threefry2x32, key=(0,42), partitionable counter scheme: bits[i] = o0 ^ o1
// ---------------------------------------------------------------------------
__device__ __forceinline__ unsigned tf_bits(unsigned ctr) {
  const unsigned k0 = 0u, k1 = 42u, k2 = 0x1BD11BDAu ^ 0u ^ 42u;
  unsigned x0 = 0u + k0;      // counts_hi = 0
  unsigned x1 = ctr + k1;     // counts_lo = ctr
#define TF_R(r) { x0 += x1; x1 = __funnelshift_l(x1, x1, r); x1 ^= x0; }
  TF_R(13) TF_R(15) TF_R(26) TF_R(6)   x0 += k1; x1 += k2 + 1u;
  TF_R(17) TF_R(29) TF_R(16) TF_R(24)  x0 += k2; x1 += k0 + 2u;
  TF_R(13) TF_R(15) TF_R(26) TF_R(6)   x0 += k0; x1 += k1 + 3u;
  TF_R(17) TF_R(29) TF_R(16) TF_R(24)  x0 += k1; x1 += k2 + 4u;
  TF_R(13) TF_R(15) TF_R(26) TF_R(6)   x0 += k2; x1 += k0 + 5u;
#undef TF_R
  return x0 ^ x1;
}

__global__ __launch_bounds__(128) void k_sample(
    const float* __restrict__ wsc, const float* __restrict__ bsc,
    float* __restrict__ out) {
  const int b = blockIdx.y;
  const int g = blockIdx.x * 128 + threadIdx.x;
  if (g >= NG) return;
  const int o = g / 25;
  const int base = (b * NGB + o) * NC;
  const unsigned i0 = (unsigned)(b * NG + g) * 7u;

  float s[NC], p[NC];
  float m = -3.0e38f;
#pragma unroll
  for (int c = 0; c < NC; c++) {
    const unsigned bits = tf_bits(i0 + (unsigned)c);
    const float u = __uint_as_float((bits >> 9) | 0x3f800000u) - 1.0f;
    const float gn = -logf(-logf(u + 1e-20f) + 1e-20f);
    p[c] = g_p[base + c];
    const float sv = (g_lp[base + c] + gn) * 10.0f;  // /TEMP, TEMP=0.1
    s[c] = sv;
    m = fmaxf(m, sv);
  }
  float e[NC], sum = 0.0f;
#pragma unroll
  for (int c = 0; c < NC; c++) { e[c] = expf(s[c] - m); sum += e[c]; }
  float y[NC], ym = 0.0f;
#pragma unroll
  for (int c = 0; c < NC; c++) { y[c] = e[c] / sum; ym = fmaxf(ym, y[c]); }
  float smp = 0.0f;
#pragma unroll
  for (int c = 0; c < NC; c++) {
    const float yh = (y[c] == ym) ? 1.0f : 0.0f;
    smp += (float)c * ((yh - y[c]) + y[c]);   // straight-through forward value
  }
  const size_t bg = (size_t)b * NG + g;
  out[OFF_SAMPLE + bg] = smp;
  const float t = smp * wsc[g] + bsc[g];
  out[OFF_MU + bg] = 1.0f / (1.0f + expf(-t));
  float* po = out + OFF_PI + bg * 7;
#pragma unroll
  for (int c = 0; c < NC; c++) po[c] = p[c];
}

// ---------------------------------------------------------------------------
extern "C" void kernel_launch(void* const* d_in, const int* in_sizes, int n_in,
                              void* d_out, int out_size) {
  const float* z   = (const float*)d_in[0];
  const float* w0  = (const float*)d_in[1];
  const float* b0  = (const float*)d_in[2];
  const float* g0  = (const float*)d_in[3];
  const float* be0 = (const float*)d_in[4];
  const float* m0  = (const float*)d_in[5];
  const float* v0  = (const float*)d_in[6];
  const float* w1  = (const float*)d_in[7];
  const float* b1  = (const float*)d_in[8];
  const float* g1  = (const float*)d_in[9];
  const float* be1 = (const float*)d_in[10];
  const float* m1  = (const float*)d_in[11];
  const float* v1  = (const float*)d_in[12];
  const float* wr  = (const float*)d_in[13];
  const float* br  = (const float*)d_in[14];
  const float* wd  = (const float*)d_in[15];
  const float* bd  = (const float*)d_in[16];
  const float* wrho= (const float*)d_in[17];
  const float* brho= (const float*)d_in[18];
  const float* wsc = (const float*)d_in[19];
  const float* bsc = (const float*)d_in[20];
  float* out = (float*)d_out;

  k_mlp<<<NB, HID>>>(z, w0, b0, g0, be0, m0, v0, w1, b1, g1, be1, m1, v1);
  dim3 gg((NG + 63) / 64, NB / 64);
  k_gemm<<<gg, 256>>>(wr, br, wd, bd, out);
  k_rho<<<NGB / 8, 256>>>(wrho, brho);
  dim3 gs((NG + 127) / 128, NB);
  k_sample<<<gs, 128>>>(wsc, bsc, out);
}

// round 5
// speedup vs baseline: 1.2530x; 1.2530x over previous
#include <cuda_runtime.h>
#include <cuda_bf16.h>
#include <cstdint>

#define NB   256
#define LAT  20
#define HID  128
#define NG   25000
#define NGB  1000
#define NC   7

// output tuple (mu, theta, pi_drop, sample, pi) concatenated, fp32
#define OFF_MU      0
#define OFF_THETA   6400000
#define OFF_PD      12800000
#define OFF_SAMPLE  19200000
#define OFF_PI      25600000

// scratch (device globals; no allocations allowed)
__device__ __align__(16) float g_x [NB * HID];   // x[b][h]
__device__ __align__(16) float g_xt[HID * NB];   // x^T[h][b]
__device__ __align__(16) float g_p [NB * NGB * NC];  // softmax(rho) as [b][o][c]
__device__ __align__(16) float g_lp[NB * NGB * NC];  // log(p + 1e-20)

// ---------------------------------------------------------------------------
// K1: x = relu(bn(relu(bn(z@w0+b0)) @ w1 + b1)), write both layouts
// ---------------------------------------------------------------------------
__global__ __launch_bounds__(HID) void k_mlp(
    const float* __restrict__ z,  const float* __restrict__ w0,
    const float* __restrict__ b0, const float* __restrict__ g0,
    const float* __restrict__ be0,const float* __restrict__ m0,
    const float* __restrict__ v0,
    const float* __restrict__ w1, const float* __restrict__ b1,
    const float* __restrict__ g1, const float* __restrict__ be1,
    const float* __restrict__ m1, const float* __restrict__ v1) {
  __shared__ float zs[LAT];
  __shared__ float xs[HID];
  const int b = blockIdx.x;
  const int h = threadIdx.x;
  if (h < LAT) zs[h] = z[b * LAT + h];
  __syncthreads();
  float acc = b0[h];
#pragma unroll
  for (int k = 0; k < LAT; k++) acc = fmaf(zs[k], w0[k * HID + h], acc);
  acc = (acc - m0[h]) * rsqrtf(v0[h] + 1e-3f) * g0[h] + be0[h];
  acc = fmaxf(acc, 0.0f);
  xs[h] = acc;
  __syncthreads();
  float a2 = b1[h];
#pragma unroll
  for (int k = 0; k < HID; k++) a2 = fmaf(xs[k], w1[k * HID + h], a2);
  a2 = (a2 - m1[h]) * rsqrtf(v1[h] + 1e-3f) * g1[h] + be1[h];
  a2 = fmaxf(a2, 0.0f);
  g_x[b * HID + h]  = a2;
  g_xt[h * NB + b]  = a2;
}

// ---------------------------------------------------------------------------
// K2: theta = exp(x@wr+br), pi_drop = x@wd+bd
// 64(batch) x 64(gene) tile, BK=32, 256 threads, 4x4 micro-tile per output
// ---------------------------------------------------------------------------
__global__ __launch_bounds__(256) void k_gemm(
    const float* __restrict__ wr, const float* __restrict__ br,
    const float* __restrict__ wd, const float* __restrict__ bd,
    float* __restrict__ out) {
  __shared__ float xs[32][68];   // [k][m], pad 68 keeps float4 16B-aligned
  __shared__ float wrs[32][64];  // [k][g]
  __shared__ float wds[32][64];
  const int tid = threadIdx.x;
  const int tx = tid & 15, ty = tid >> 4;
  const int g0 = blockIdx.x * 64;
  const int m0 = blockIdx.y * 64;
  float aT[4][4] = {}, aD[4][4] = {};

  for (int kc = 0; kc < HID; kc += 32) {
    const int c = tid & 31, r0 = tid >> 5;
#pragma unroll
    for (int t = 0; t < 8; t++) {
      const int r = r0 + t * 8;
      xs[c][r] = g_x[(m0 + r) * HID + kc + c];
    }
    const int j = tid & 63, kk0 = tid >> 6;
#pragma unroll
    for (int t = 0; t < 8; t++) {
      const int kk = kk0 + t * 4;
      const int g = g0 + j;
      const bool ok = (g < NG);
      wrs[kk][j] = ok ? wr[(kc + kk) * NG + g] : 0.0f;
      wds[kk][j] = ok ? wd[(kc + kk) * NG + g] : 0.0f;
    }
    __syncthreads();
#pragma unroll
    for (int k = 0; k < 32; k++) {
      const float4 av  = *(const float4*)&xs[k][ty * 4];
      const float4 brv = *(const float4*)&wrs[k][tx * 4];
      const float4 bdv = *(const float4*)&wds[k][tx * 4];
      const float a[4]  = {av.x, av.y, av.z, av.w};
      const float wrv4[4] = {brv.x, brv.y, brv.z, brv.w};
      const float wdv4[4] = {bdv.x, bdv.y, bdv.z, bdv.w};
#pragma unroll
      for (int i = 0; i < 4; i++)
#pragma unroll
        for (int jj = 0; jj < 4; jj++) {
          aT[i][jj] = fmaf(a[i], wrv4[jj], aT[i][jj]);
          aD[i][jj] = fmaf(a[i], wdv4[jj], aD[i][jj]);
        }
    }
    __syncthreads();
  }
#pragma unroll
  for (int jj = 0; jj < 4; jj++) {
    const int g = g0 + tx * 4 + jj;
    if (g >= NG) continue;
    const float brv = br[g], bdv = bd[g];
#pragma unroll
    for (int i = 0; i < 4; i++) {
      const int mrow = m0 + ty * 4 + i;
      const size_t idx = (size_t)mrow * NG + g;
      out[OFF_THETA + idx] = __expf(aT[i][jj] + brv);
      out[OFF_PD + idx]    = aD[i][jj] + bdv;
    }
  }
}

// ---------------------------------------------------------------------------
// K3: rho[c][b][o] = x@wrho[c] + brho[c]; softmax over c; store p and log(p+eps)
// 125 blocks x 8 o-cols each, 256 threads = batch dim, acc[7][8] in regs
// ---------------------------------------------------------------------------
__global__ __launch_bounds__(256) void k_rho(
    const float* __restrict__ wrho, const float* __restrict__ brho) {
  __shared__ float ws[NC * HID * 8];  // [c][h][j] contiguous = 28 KB
  const int tid = threadIdx.x;
  const int b = tid;
  const int o0 = blockIdx.x * 8;
  for (int idx = tid; idx < NC * HID * 8; idx += 256) {
    const int c = idx >> 10;
    const int rem = idx & 1023;
    const int h = rem >> 3, j = rem & 7;
    ws[idx] = wrho[c * HID * NGB + h * NGB + o0 + j];
  }
  __syncthreads();

  float acc[NC][8] = {};
  for (int h = 0; h < HID; h++) {
    const float xv = g_xt[h * NB + b];
#pragma unroll
    for (int c = 0; c < NC; c++) {
      const float4* wp = (const float4*)&ws[(c * HID + h) * 8];
      const float4 w0 = wp[0], w1 = wp[1];
      acc[c][0] = fmaf(xv, w0.x, acc[c][0]);
      acc[c][1] = fmaf(xv, w0.y, acc[c][1]);
      acc[c][2] = fmaf(xv, w0.z, acc[c][2]);
      acc[c][3] = fmaf(xv, w0.w, acc[c][3]);
      acc[c][4] = fmaf(xv, w1.x, acc[c][4]);
      acc[c][5] = fmaf(xv, w1.y, acc[c][5]);
      acc[c][6] = fmaf(xv, w1.z, acc[c][6]);
      acc[c][7] = fmaf(xv, w1.w, acc[c][7]);
    }
  }
#pragma unroll
  for (int j = 0; j < 8; j++) {
    float v[NC];
    float m = -3.0e38f;
#pragma unroll
    for (int c = 0; c < NC; c++) {
      v[c] = acc[c][j] + brho[c * NGB + o0 + j];
      m = fmaxf(m, v[c]);
    }
    float e[NC], sum = 0.0f;
#pragma unroll
    for (int c = 0; c < NC; c++) { e[c] = expf(v[c] - m); sum += e[c]; }
    const int base = (b * NGB + o0 + j) * NC;
#pragma unroll
    for (int c = 0; c < NC; c++) {
      const float p = e[c] / sum;
      g_p[base + c]  = p;
      g_lp[base + c] = logf(p + 1e-20f);
    }
  }
}

// ---------------------------------------------------------------------------
// K4: Gumbel-softmax straight-through sampler + mu + pi output
// threefry2x32, key=(0,42), partitionable counter scheme: bits[i] = o0 ^ o1
// Fast-math transcendentals: sample output is argmax-dominated, so MUFU-level
// precision (~1e-6) cannot flip results except on exact ties.
// ---------------------------------------------------------------------------
__device__ __forceinline__ unsigned tf_bits(unsigned ctr) {
  const unsigned k0 = 0u, k1 = 42u, k2 = 0x1BD11BDAu ^ 0u ^ 42u;
  unsigned x0 = 0u + k0;      // counts_hi = 0
  unsigned x1 = ctr + k1;     // counts_lo = ctr
#define TF_R(r) { x0 += x1; x1 = __funnelshift_l(x1, x1, r); x1 ^= x0; }
  TF_R(13) TF_R(15) TF_R(26) TF_R(6)   x0 += k1; x1 += k2 + 1u;
  TF_R(17) TF_R(29) TF_R(16) TF_R(24)  x0 += k2; x1 += k0 + 2u;
  TF_R(13) TF_R(15) TF_R(26) TF_R(6)   x0 += k0; x1 += k1 + 3u;
  TF_R(17) TF_R(29) TF_R(16) TF_R(24)  x0 += k1; x1 += k2 + 4u;
  TF_R(13) TF_R(15) TF_R(26) TF_R(6)   x0 += k2; x1 += k0 + 5u;
#undef TF_R
  return x0 ^ x1;
}

__global__ __launch_bounds__(128) void k_sample(
    const float* __restrict__ wsc, const float* __restrict__ bsc,
    float* __restrict__ out) {
  const int b = blockIdx.y;
  const int g = blockIdx.x * 128 + threadIdx.x;
  if (g >= NG) return;
  const int o = g / 25;
  const int base = (b * NGB + o) * NC;
  const unsigned i0 = (unsigned)(b * NG + g) * 7u;

  float s[NC];
  float m = -3.0e38f;
#pragma unroll
  for (int c = 0; c < NC; c++) {
    const unsigned bits = tf_bits(i0 + (unsigned)c);
    const float u = __uint_as_float((bits >> 9) | 0x3f800000u) - 1.0f;
    const float gn = -__logf(-__logf(u + 1e-20f) + 1e-20f);
    const float sv = (__ldg(&g_lp[base + c]) + gn) * 10.0f;  // /TEMP, TEMP=0.1
    s[c] = sv;
    m = fmaxf(m, sv);
  }
  float e[NC], sum = 0.0f;
#pragma unroll
  for (int c = 0; c < NC; c++) { e[c] = __expf(s[c] - m); sum += e[c]; }
  const float rinv = __fdividef(1.0f, sum);
  float y[NC], ym = 0.0f;
#pragma unroll
  for (int c = 0; c < NC; c++) { y[c] = e[c] * rinv; ym = fmaxf(ym, y[c]); }
  float smp = 0.0f;
#pragma unroll
  for (int c = 0; c < NC; c++) {
    const float yh = (y[c] == ym) ? 1.0f : 0.0f;
    smp += (float)c * ((yh - y[c]) + y[c]);   // straight-through forward value
  }
  const size_t bg = (size_t)b * NG + g;
  out[OFF_SAMPLE + bg] = smp;
  const float t = smp * wsc[g] + bsc[g];
  out[OFF_MU + bg] = __fdividef(1.0f, 1.0f + __expf(-t));
  float* po = out + OFF_PI + bg * 7;
#pragma unroll
  for (int c = 0; c < NC; c++) po[c] = __ldg(&g_p[base + c]);
}

// ---------------------------------------------------------------------------
extern "C" void kernel_launch(void* const* d_in, const int* in_sizes, int n_in,
                              void* d_out, int out_size) {
  const float* z   = (const float*)d_in[0];
  const float* w0  = (const float*)d_in[1];
  const float* b0  = (const float*)d_in[2];
  const float* g0  = (const float*)d_in[3];
  const float* be0 = (const float*)d_in[4];
  const float* m0  = (const float*)d_in[5];
  const float* v0  = (const float*)d_in[6];
  const float* w1  = (const float*)d_in[7];
  const float* b1  = (const float*)d_in[8];
  const float* g1  = (const float*)d_in[9];
  const float* be1 = (const float*)d_in[10];
  const float* m1  = (const float*)d_in[11];
  const float* v1  = (const float*)d_in[12];
  const float* wr  = (const float*)d_in[13];
  const float* br  = (const float*)d_in[14];
  const float* wd  = (const float*)d_in[15];
  const float* bd  = (const float*)d_in[16];
  const float* wrho= (const float*)d_in[17];
  const float* brho= (const float*)d_in[18];
  const float* wsc = (const float*)d_in[19];
  const float* bsc = (const float*)d_in[20];
  float* out = (float*)d_out;

  k_mlp<<<NB, HID>>>(z, w0, b0, g0, be0, m0, v0, w1, b1, g1, be1, m1, v1);
  dim3 gg((NG + 63) / 64, NB / 64);
  k_gemm<<<gg, 256>>>(wr, br, wd, bd, out);
  k_rho<<<NGB / 8, 256>>>(wrho, brho);
  dim3 gs((NG + 127) / 128, NB);
  k_sample<<<gs, 128>>>(wsc, bsc, out);
}

// round 6
// speedup vs baseline: 1.3745x; 1.0970x over previous
#include <cuda_runtime.h>
#include <cuda_bf16.h>
#include <cstdint>

#define NB   256
#define LAT  20
#define HID  128
#define NG   25000
#define NGB  1000
#define NC   7

// output tuple (mu, theta, pi_drop, sample, pi) concatenated, fp32
#define OFF_MU      0
#define OFF_THETA   6400000
#define OFF_PD      12800000
#define OFF_SAMPLE  19200000
#define OFF_PI      25600000

// scratch (device globals; no allocations allowed)
__device__ __align__(16) float g_x [NB * HID];   // x[b][h]
__device__ __align__(16) float g_xt[HID * NB];   // x^T[h][b]
// per (b,o): floats [0..6]=p, [8..14]=log(p+1e-20), padded to 16 for LDG.128
__device__ __align__(16) float g_pp[NB * NGB * 16];

// ---------------------------------------------------------------------------
// packed fp32x2 helpers (Blackwell FFMA2 — IEEE-exact lanewise, 2 FMA / issue)
// ---------------------------------------------------------------------------
typedef unsigned long long F2;
__device__ __forceinline__ F2 pack2(float lo, float hi) {
  F2 r; asm("mov.b64 %0, {%1, %2};" : "=l"(r) : "f"(lo), "f"(hi)); return r;
}
__device__ __forceinline__ void unpack2(F2 v, float& lo, float& hi) {
  asm("mov.b64 {%0, %1}, %2;" : "=f"(lo), "=f"(hi) : "l"(v));
}
__device__ __forceinline__ F2 ffma2(F2 a, F2 b, F2 c) {
  F2 d; asm("fma.rn.f32x2 %0, %1, %2, %3;" : "=l"(d) : "l"(a), "l"(b), "l"(c));
  return d;
}

// ---------------------------------------------------------------------------
// K1: x = relu(bn(relu(bn(z@w0+b0)) @ w1 + b1)), write both layouts
// ---------------------------------------------------------------------------
__global__ __launch_bounds__(HID) void k_mlp(
    const float* __restrict__ z,  const float* __restrict__ w0,
    const float* __restrict__ b0, const float* __restrict__ g0,
    const float* __restrict__ be0,const float* __restrict__ m0,
    const float* __restrict__ v0,
    const float* __restrict__ w1, const float* __restrict__ b1,
    const float* __restrict__ g1, const float* __restrict__ be1,
    const float* __restrict__ m1, const float* __restrict__ v1) {
  __shared__ float zs[LAT];
  __shared__ float xs[HID];
  const int b = blockIdx.x;
  const int h = threadIdx.x;
  if (h < LAT) zs[h] = z[b * LAT + h];
  __syncthreads();
  float acc = b0[h];
#pragma unroll
  for (int k = 0; k < LAT; k++) acc = fmaf(zs[k], w0[k * HID + h], acc);
  acc = (acc - m0[h]) * rsqrtf(v0[h] + 1e-3f) * g0[h] + be0[h];
  acc = fmaxf(acc, 0.0f);
  xs[h] = acc;
  __syncthreads();
  float a2 = b1[h];
#pragma unroll
  for (int k = 0; k < HID; k++) a2 = fmaf(xs[k], w1[k * HID + h], a2);
  a2 = (a2 - m1[h]) * rsqrtf(v1[h] + 1e-3f) * g1[h] + be1[h];
  a2 = fmaxf(a2, 0.0f);
  g_x[b * HID + h]  = a2;
  g_xt[h * NB + b]  = a2;
}

// ---------------------------------------------------------------------------
// K2: theta = exp(x@wr+br), pi_drop = x@wd+bd
// 64(batch) x 64(gene) tile, BK=32, 256 threads, 4x4 micro-tile, FFMA2 inner
// ---------------------------------------------------------------------------
__global__ __launch_bounds__(256) void k_gemm(
    const float* __restrict__ wr, const float* __restrict__ br,
    const float* __restrict__ wd, const float* __restrict__ bd,
    float* __restrict__ out) {
  __shared__ float xs[32][68];   // [k][m], pad 68 keeps float4 16B-aligned
  __shared__ float wrs[32][64];  // [k][g]
  __shared__ float wds[32][64];
  const int tid = threadIdx.x;
  const int tx = tid & 15, ty = tid >> 4;
  const int g0 = blockIdx.x * 64;
  const int m0 = blockIdx.y * 64;
  F2 aT2[4][2], aD2[4][2];
#pragma unroll
  for (int i = 0; i < 4; i++) {
    aT2[i][0] = aT2[i][1] = 0ull;
    aD2[i][0] = aD2[i][1] = 0ull;
  }

  for (int kc = 0; kc < HID; kc += 32) {
    const int c = tid & 31, r0 = tid >> 5;
#pragma unroll
    for (int t = 0; t < 8; t++) {
      const int r = r0 + t * 8;
      xs[c][r] = g_x[(m0 + r) * HID + kc + c];
    }
    const int j = tid & 63, kk0 = tid >> 6;
#pragma unroll
    for (int t = 0; t < 8; t++) {
      const int kk = kk0 + t * 4;
      const int g = g0 + j;
      const bool ok = (g < NG);
      wrs[kk][j] = ok ? wr[(kc + kk) * NG + g] : 0.0f;
      wds[kk][j] = ok ? wd[(kc + kk) * NG + g] : 0.0f;
    }
    __syncthreads();
#pragma unroll
    for (int k = 0; k < 32; k++) {
      const float4 av = *(const float4*)&xs[k][ty * 4];
      const F2 wr0 = *(const F2*)&wrs[k][tx * 4];
      const F2 wr1 = *(const F2*)&wrs[k][tx * 4 + 2];
      const F2 wd0 = *(const F2*)&wds[k][tx * 4];
      const F2 wd1 = *(const F2*)&wds[k][tx * 4 + 2];
      const F2 a0 = pack2(av.x, av.x);
      const F2 a1 = pack2(av.y, av.y);
      const F2 a2 = pack2(av.z, av.z);
      const F2 a3 = pack2(av.w, av.w);
      aT2[0][0] = ffma2(a0, wr0, aT2[0][0]); aT2[0][1] = ffma2(a0, wr1, aT2[0][1]);
      aT2[1][0] = ffma2(a1, wr0, aT2[1][0]); aT2[1][1] = ffma2(a1, wr1, aT2[1][1]);
      aT2[2][0] = ffma2(a2, wr0, aT2[2][0]); aT2[2][1] = ffma2(a2, wr1, aT2[2][1]);
      aT2[3][0] = ffma2(a3, wr0, aT2[3][0]); aT2[3][1] = ffma2(a3, wr1, aT2[3][1]);
      aD2[0][0] = ffma2(a0, wd0, aD2[0][0]); aD2[0][1] = ffma2(a0, wd1, aD2[0][1]);
      aD2[1][0] = ffma2(a1, wd0, aD2[1][0]); aD2[1][1] = ffma2(a1, wd1, aD2[1][1]);
      aD2[2][0] = ffma2(a2, wd0, aD2[2][0]); aD2[2][1] = ffma2(a2, wd1, aD2[2][1]);
      aD2[3][0] = ffma2(a3, wd0, aD2[3][0]); aD2[3][1] = ffma2(a3, wd1, aD2[3][1]);
    }
    __syncthreads();
  }
#pragma unroll
  for (int i = 0; i < 4; i++) {
    float t[4], d[4];
    unpack2(aT2[i][0], t[0], t[1]); unpack2(aT2[i][1], t[2], t[3]);
    unpack2(aD2[i][0], d[0], d[1]); unpack2(aD2[i][1], d[2], d[3]);
    const int mrow = m0 + ty * 4 + i;
#pragma unroll
    for (int jj = 0; jj < 4; jj++) {
      const int g = g0 + tx * 4 + jj;
      if (g >= NG) continue;
      const size_t idx = (size_t)mrow * NG + g;
      out[OFF_THETA + idx] = __expf(t[jj] + br[g]);
      out[OFF_PD + idx]    = d[jj] + bd[g];
    }
  }
}

// ---------------------------------------------------------------------------
// K3: rho[c][b][o] = x@wrho[c] + brho[c]; softmax over c; store p / log(p+eps)
// 125 blocks x 8 o-cols each, 256 threads = batch dim, FFMA2 accumulators
// ---------------------------------------------------------------------------
__global__ __launch_bounds__(256) void k_rho(
    const float* __restrict__ wrho, const float* __restrict__ brho) {
  __shared__ float ws[NC * HID * 8];  // [c][h][j] contiguous = 28 KB
  const int tid = threadIdx.x;
  const int b = tid;
  const int o0 = blockIdx.x * 8;
  for (int idx = tid; idx < NC * HID * 8; idx += 256) {
    const int c = idx >> 10;
    const int rem = idx & 1023;
    const int h = rem >> 3, j = rem & 7;
    ws[idx] = wrho[c * HID * NGB + h * NGB + o0 + j];
  }
  __syncthreads();

  F2 acc2[NC][4];
#pragma unroll
  for (int c = 0; c < NC; c++)
#pragma unroll
    for (int q = 0; q < 4; q++) acc2[c][q] = 0ull;

  for (int h = 0; h < HID; h++) {
    const float xv = g_xt[h * NB + b];
    const F2 xp = pack2(xv, xv);
#pragma unroll
    for (int c = 0; c < NC; c++) {
      const F2* wp = (const F2*)&ws[(c * HID + h) * 8];
      acc2[c][0] = ffma2(xp, wp[0], acc2[c][0]);
      acc2[c][1] = ffma2(xp, wp[1], acc2[c][1]);
      acc2[c][2] = ffma2(xp, wp[2], acc2[c][2]);
      acc2[c][3] = ffma2(xp, wp[3], acc2[c][3]);
    }
  }
  float acc[NC][8];
#pragma unroll
  for (int c = 0; c < NC; c++)
#pragma unroll
    for (int q = 0; q < 4; q++) unpack2(acc2[c][q], acc[c][2 * q], acc[c][2 * q + 1]);

#pragma unroll
  for (int j = 0; j < 8; j++) {
    float v[NC];
    float m = -3.0e38f;
#pragma unroll
    for (int c = 0; c < NC; c++) {
      v[c] = acc[c][j] + brho[c * NGB + o0 + j];
      m = fmaxf(m, v[c]);
    }
    float e[NC], sum = 0.0f;
#pragma unroll
    for (int c = 0; c < NC; c++) { e[c] = expf(v[c] - m); sum += e[c]; }
    const int base = (b * NGB + o0 + j) * 16;
#pragma unroll
    for (int c = 0; c < NC; c++) {
      const float p = e[c] / sum;
      g_pp[base + c]     = p;
      g_pp[base + 8 + c] = logf(p + 1e-20f);
    }
    g_pp[base + 7] = 0.0f; g_pp[base + 15] = 0.0f;
  }
}

// ---------------------------------------------------------------------------
// K4: Gumbel-softmax straight-through sampler + mu + pi output
// threefry2x32, key=(0,42), partitionable counters: bits[i] = o0 ^ o1
// ---------------------------------------------------------------------------
__device__ __forceinline__ unsigned tf_bits(unsigned ctr) {
  const unsigned k0 = 0u, k1 = 42u, k2 = 0x1BD11BDAu ^ 0u ^ 42u;
  unsigned x0 = 0u + k0;      // counts_hi = 0
  unsigned x1 = ctr + k1;     // counts_lo = ctr
#define TF_R(r) { x0 += x1; x1 = __funnelshift_l(x1, x1, r); x1 ^= x0; }
  TF_R(13) TF_R(15) TF_R(26) TF_R(6)   x0 += k1; x1 += k2 + 1u;
  TF_R(17) TF_R(29) TF_R(16) TF_R(24)  x0 += k2; x1 += k0 + 2u;
  TF_R(13) TF_R(15) TF_R(26) TF_R(6)   x0 += k0; x1 += k1 + 3u;
  TF_R(17) TF_R(29) TF_R(16) TF_R(24)  x0 += k1; x1 += k2 + 4u;
  TF_R(13) TF_R(15) TF_R(26) TF_R(6)   x0 += k2; x1 += k0 + 5u;
#undef TF_R
  return x0 ^ x1;
}

__global__ __launch_bounds__(128) void k_sample(
    const float* __restrict__ wsc, const float* __restrict__ bsc,
    float* __restrict__ out) {
  const int b = blockIdx.y;
  const int g = blockIdx.x * 128 + threadIdx.x;
  if (g >= NG) return;
  const int o = g / 25;
  const float4* pp = (const float4*)&g_pp[(b * NGB + o) * 16];
  const float4 pv0 = __ldg(pp + 0), pv1 = __ldg(pp + 1);
  const float4 lv0 = __ldg(pp + 2), lv1 = __ldg(pp + 3);
  const float p[NC]  = {pv0.x, pv0.y, pv0.z, pv0.w, pv1.x, pv1.y, pv1.z};
  const float lp[NC] = {lv0.x, lv0.y, lv0.z, lv0.w, lv1.x, lv1.y, lv1.z};
  const unsigned i0 = (unsigned)(b * NG + g) * 7u;

  float s[NC];
  float m = -3.0e38f;
#pragma unroll
  for (int c = 0; c < NC; c++) {
    const unsigned bits = tf_bits(i0 + (unsigned)c);
    const float u = __uint_as_float((bits >> 9) | 0x3f800000u) - 1.0f;
    const float gn = -__logf(-__logf(u + 1e-20f) + 1e-20f);
    const float sv = (lp[c] + gn) * 10.0f;  // /TEMP, TEMP=0.1
    s[c] = sv;
    m = fmaxf(m, sv);
  }
  float e[NC], sum = 0.0f;
#pragma unroll
  for (int c = 0; c < NC; c++) { e[c] = __expf(s[c] - m); sum += e[c]; }
  const float rinv = __fdividef(1.0f, sum);
  float y[NC], ym = 0.0f;
#pragma unroll
  for (int c = 0; c < NC; c++) { y[c] = e[c] * rinv; ym = fmaxf(ym, y[c]); }
  float smp = 0.0f;
#pragma unroll
  for (int c = 0; c < NC; c++) {
    const float yh = (y[c] == ym) ? 1.0f : 0.0f;
    smp += (float)c * ((yh - y[c]) + y[c]);   // straight-through forward value
  }
  const size_t bg = (size_t)b * NG + g;
  out[OFF_SAMPLE + bg] = smp;
  const float t = smp * wsc[g] + bsc[g];
  out[OFF_MU + bg] = __fdividef(1.0f, 1.0f + __expf(-t));
  float* po = out + OFF_PI + bg * 7;
#pragma unroll
  for (int c = 0; c < NC; c++) po[c] = p[c];
}

// ---------------------------------------------------------------------------
extern "C" void kernel_launch(void* const* d_in, const int* in_sizes, int n_in,
                              void* d_out, int out_size) {
  const float* z   = (const float*)d_in[0];
  const float* w0  = (const float*)d_in[1];
  const float* b0  = (const float*)d_in[2];
  const float* g0  = (const float*)d_in[3];
  const float* be0 = (const float*)d_in[4];
  const float* m0  = (const float*)d_in[5];
  const float* v0  = (const float*)d_in[6];
  const float* w1  = (const float*)d_in[7];
  const float* b1  = (const float*)d_in[8];
  const float* g1  = (const float*)d_in[9];
  const float* be1 = (const float*)d_in[10];
  const float* m1  = (const float*)d_in[11];
  const float* v1  = (const float*)d_in[12];
  const float* wr  = (const float*)d_in[13];
  const float* br  = (const float*)d_in[14];
  const float* wd  = (const float*)d_in[15];
  const float* bd  = (const float*)d_in[16];
  const float* wrho= (const float*)d_in[17];
  const float* brho= (const float*)d_in[18];
  const float* wsc = (const float*)d_in[19];
  const float* bsc = (const float*)d_in[20];
  float* out = (float*)d_out;

  k_mlp<<<NB, HID>>>(z, w0, b0, g0, be0, m0, v0, w1, b1, g1, be1, m1, v1);
  dim3 gg((NG + 63) / 64, NB / 64);
  k_gemm<<<gg, 256>>>(wr, br, wd, bd, out);
  k_rho<<<NGB / 8, 256>>>(wrho, brho);
  dim3 gs((NG + 127) / 128, NB);
  k_sample<<<gs, 128>>>(wsc, bsc, out);
}

// round 7
// speedup vs baseline: 1.5720x; 1.1437x over previous
#include <cuda_runtime.h>
#include <cuda_bf16.h>
#include <cstdint>

#define NB   256
#define LAT  20
#define HID  128
#define NG   25000
#define NGB  1000
#define NC   7

// output tuple (mu, theta, pi_drop, sample, pi) concatenated, fp32
#define OFF_MU      0
#define OFF_THETA   6400000
#define OFF_PD      12800000
#define OFF_SAMPLE  19200000
#define OFF_PI      25600000

// scratch (device globals; no allocations allowed)
__device__ __align__(16) float g_xt[HID * NB];   // x^T[h][b]
// per (b,o): floats [0..6]=p, [8..14]=log(p+1e-20), padded to 16 for LDG.128
__device__ __align__(16) float g_pp[NB * NGB * 16];

// ---------------------------------------------------------------------------
// packed fp32x2 helpers (Blackwell FFMA2 — IEEE-exact lanewise, 2 FMA / issue)
// ---------------------------------------------------------------------------
typedef unsigned long long F2;
__device__ __forceinline__ F2 pack2(float lo, float hi) {
  F2 r; asm("mov.b64 %0, {%1, %2};" : "=l"(r) : "f"(lo), "f"(hi)); return r;
}
__device__ __forceinline__ void unpack2(F2 v, float& lo, float& hi) {
  asm("mov.b64 {%0, %1}, %2;" : "=f"(lo), "=f"(hi) : "l"(v));
}
__device__ __forceinline__ F2 ffma2(F2 a, F2 b, F2 c) {
  F2 d; asm("fma.rn.f32x2 %0, %1, %2, %3;" : "=l"(d) : "l"(a), "l"(b), "l"(c));
  return d;
}

// ---------------------------------------------------------------------------
// K1: x = relu(bn(relu(bn(z@w0+b0)) @ w1 + b1)) -> g_xt (k-major)
// ---------------------------------------------------------------------------
__global__ __launch_bounds__(HID) void k_mlp(
    const float* __restrict__ z,  const float* __restrict__ w0,
    const float* __restrict__ b0, const float* __restrict__ g0,
    const float* __restrict__ be0,const float* __restrict__ m0,
    const float* __restrict__ v0,
    const float* __restrict__ w1, const float* __restrict__ b1,
    const float* __restrict__ g1, const float* __restrict__ be1,
    const float* __restrict__ m1, const float* __restrict__ v1) {
  __shared__ float zs[LAT];
  __shared__ float xs[HID];
  const int b = blockIdx.x;
  const int h = threadIdx.x;
  if (h < LAT) zs[h] = z[b * LAT + h];
  __syncthreads();
  float acc = b0[h];
#pragma unroll
  for (int k = 0; k < LAT; k++) acc = fmaf(zs[k], w0[k * HID + h], acc);
  acc = (acc - m0[h]) * rsqrtf(v0[h] + 1e-3f) * g0[h] + be0[h];
  acc = fmaxf(acc, 0.0f);
  xs[h] = acc;
  __syncthreads();
  float a2 = b1[h];
#pragma unroll
  for (int k = 0; k < HID; k++) a2 = fmaf(xs[k], w1[k * HID + h], a2);
  a2 = (a2 - m1[h]) * rsqrtf(v1[h] + 1e-3f) * g1[h] + be1[h];
  a2 = fmaxf(a2, 0.0f);
  g_xt[h * NB + b] = a2;
}

// ---------------------------------------------------------------------------
// K2: theta = exp(x@wr+br), pi_drop = x@wd+bd
// BM=128 x BN=64 x BK=32, 256 threads, thread tile 8b x 4g x 2 matrices.
// Per SM per k: LDS 128 cyc == FMA 128 cyc (balanced at the fma floor).
// ---------------------------------------------------------------------------
#define BM 128
#define BN 64
#define BK 32
__global__ __launch_bounds__(256) void k_gemm(
    const float* __restrict__ wr, const float* __restrict__ br,
    const float* __restrict__ wd, const float* __restrict__ bd,
    float* __restrict__ out) {
  __shared__ float xs[BK][BM];    // 16 KB, [k][m], conflict-free both phases
  __shared__ float wrs[BK][BN];   // 8 KB
  __shared__ float wds[BK][BN];   // 8 KB
  const int tid = threadIdx.x;
  const int tx = tid & 15;        // gene group (4 genes)
  const int ty = tid >> 4;        // batch group (8 batches)
  const int g0 = blockIdx.x * BN;
  const int m0 = blockIdx.y * BM;

  F2 aT2[8][2], aD2[8][2];
#pragma unroll
  for (int i = 0; i < 8; i++) {
    aT2[i][0] = aT2[i][1] = 0ull;
    aD2[i][0] = aD2[i][1] = 0ull;
  }

  for (int kc = 0; kc < HID; kc += BK) {
    // x tile from g_xt (k-major): coalesced LDG.128, conflict-free STS.128
    {
      const int m4 = (tid & 31) * 4;
      const int kk0 = tid >> 5;
#pragma unroll
      for (int t = 0; t < 4; t++) {
        const int kk = kk0 + t * 8;
        *(float4*)&xs[kk][m4] =
            *(const float4*)&g_xt[(kc + kk) * NB + m0 + m4];
      }
    }
    // weight tiles: coalesced LDG.128, conflict-free STS.128
    {
      const int j4 = (tid & 15) * 4;
      const int kk0 = tid >> 4;
#pragma unroll
      for (int t = 0; t < 2; t++) {
        const int kk = kk0 + t * 16;
        const int g = g0 + j4;
        float4 vr, vd;
        if (g + 3 < NG) {
          vr = *(const float4*)&wr[(size_t)(kc + kk) * NG + g];
          vd = *(const float4*)&wd[(size_t)(kc + kk) * NG + g];
        } else {
          float r[4], d[4];
#pragma unroll
          for (int q = 0; q < 4; q++) {
            const bool ok = (g + q < NG);
            r[q] = ok ? wr[(size_t)(kc + kk) * NG + g + q] : 0.0f;
            d[q] = ok ? wd[(size_t)(kc + kk) * NG + g + q] : 0.0f;
          }
          vr = make_float4(r[0], r[1], r[2], r[3]);
          vd = make_float4(d[0], d[1], d[2], d[3]);
        }
        *(float4*)&wrs[kk][j4] = vr;
        *(float4*)&wds[kk][j4] = vd;
      }
    }
    __syncthreads();
#pragma unroll
    for (int k = 0; k < BK; k++) {
      const float4 a0 = *(const float4*)&xs[k][ty * 8];
      const float4 a1 = *(const float4*)&xs[k][ty * 8 + 4];
      const F2 w0 = *(const F2*)&wrs[k][tx * 4];
      const F2 w1 = *(const F2*)&wrs[k][tx * 4 + 2];
      const F2 d0 = *(const F2*)&wds[k][tx * 4];
      const F2 d1 = *(const F2*)&wds[k][tx * 4 + 2];
      const float a[8] = {a0.x, a0.y, a0.z, a0.w, a1.x, a1.y, a1.z, a1.w};
#pragma unroll
      for (int i = 0; i < 8; i++) {
        const F2 ap = pack2(a[i], a[i]);
        aT2[i][0] = ffma2(ap, w0, aT2[i][0]);
        aT2[i][1] = ffma2(ap, w1, aT2[i][1]);
        aD2[i][0] = ffma2(ap, d0, aD2[i][0]);
        aD2[i][1] = ffma2(ap, d1, aD2[i][1]);
      }
    }
    __syncthreads();
  }

  // epilogue
  const int gbase = g0 + tx * 4;
  const bool full = (gbase + 3 < NG);
  float brv[4] = {}, bdv[4] = {};
#pragma unroll
  for (int q = 0; q < 4; q++)
    if (gbase + q < NG) { brv[q] = br[gbase + q]; bdv[q] = bd[gbase + q]; }
#pragma unroll
  for (int i = 0; i < 8; i++) {
    float t[4], d[4];
    unpack2(aT2[i][0], t[0], t[1]); unpack2(aT2[i][1], t[2], t[3]);
    unpack2(aD2[i][0], d[0], d[1]); unpack2(aD2[i][1], d[2], d[3]);
    const int mrow = m0 + ty * 8 + i;
    const size_t idx = (size_t)mrow * NG + gbase;
    if (full) {
      float4 to = make_float4(__expf(t[0] + brv[0]), __expf(t[1] + brv[1]),
                              __expf(t[2] + brv[2]), __expf(t[3] + brv[3]));
      float4 po = make_float4(d[0] + bdv[0], d[1] + bdv[1],
                              d[2] + bdv[2], d[3] + bdv[3]);
      *(float4*)&out[OFF_THETA + idx] = to;
      *(float4*)&out[OFF_PD + idx]    = po;
    } else {
#pragma unroll
      for (int q = 0; q < 4; q++) {
        if (gbase + q >= NG) continue;
        out[OFF_THETA + idx + q] = __expf(t[q] + brv[q]);
        out[OFF_PD + idx + q]    = d[q] + bdv[q];
      }
    }
  }
}

// ---------------------------------------------------------------------------
// K3: rho[c][b][o] = x@wrho[c] + brho[c]; softmax over c; store p / log(p+eps)
// ---------------------------------------------------------------------------
__global__ __launch_bounds__(256) void k_rho(
    const float* __restrict__ wrho, const float* __restrict__ brho) {
  __shared__ float ws[NC * HID * 8];  // [c][h][j] contiguous = 28 KB
  const int tid = threadIdx.x;
  const int b = tid;
  const int o0 = blockIdx.x * 8;
  for (int idx = tid; idx < NC * HID * 8; idx += 256) {
    const int c = idx >> 10;
    const int rem = idx & 1023;
    const int h = rem >> 3, j = rem & 7;
    ws[idx] = wrho[c * HID * NGB + h * NGB + o0 + j];
  }
  __syncthreads();

  F2 acc2[NC][4];
#pragma unroll
  for (int c = 0; c < NC; c++)
#pragma unroll
    for (int q = 0; q < 4; q++) acc2[c][q] = 0ull;

  for (int h = 0; h < HID; h++) {
    const float xv = g_xt[h * NB + b];
    const F2 xp = pack2(xv, xv);
#pragma unroll
    for (int c = 0; c < NC; c++) {
      const F2* wp = (const F2*)&ws[(c * HID + h) * 8];
      acc2[c][0] = ffma2(xp, wp[0], acc2[c][0]);
      acc2[c][1] = ffma2(xp, wp[1], acc2[c][1]);
      acc2[c][2] = ffma2(xp, wp[2], acc2[c][2]);
      acc2[c][3] = ffma2(xp, wp[3], acc2[c][3]);
    }
  }
  float acc[NC][8];
#pragma unroll
  for (int c = 0; c < NC; c++)
#pragma unroll
    for (int q = 0; q < 4; q++) unpack2(acc2[c][q], acc[c][2 * q], acc[c][2 * q + 1]);

#pragma unroll
  for (int j = 0; j < 8; j++) {
    float v[NC];
    float m = -3.0e38f;
#pragma unroll
    for (int c = 0; c < NC; c++) {
      v[c] = acc[c][j] + brho[c * NGB + o0 + j];
      m = fmaxf(m, v[c]);
    }
    float e[NC], sum = 0.0f;
#pragma unroll
    for (int c = 0; c < NC; c++) { e[c] = expf(v[c] - m); sum += e[c]; }
    const int base = (b * NGB + o0 + j) * 16;
#pragma unroll
    for (int c = 0; c < NC; c++) {
      const float p = e[c] / sum;
      g_pp[base + c]     = p;
      g_pp[base + 8 + c] = logf(p + 1e-20f);
    }
    g_pp[base + 7] = 0.0f; g_pp[base + 15] = 0.0f;
  }
}

// ---------------------------------------------------------------------------
// K4: Gumbel-softmax straight-through sampler + mu + pi output
// threefry2x32, key=(0,42), partitionable counters: bits[i] = o0 ^ o1
// ---------------------------------------------------------------------------
__device__ __forceinline__ unsigned tf_bits(unsigned ctr) {
  const unsigned k0 = 0u, k1 = 42u, k2 = 0x1BD11BDAu ^ 0u ^ 42u;
  unsigned x0 = 0u + k0;      // counts_hi = 0
  unsigned x1 = ctr + k1;     // counts_lo = ctr
#define TF_R(r) { x0 += x1; x1 = __funnelshift_l(x1, x1, r); x1 ^= x0; }
  TF_R(13) TF_R(15) TF_R(26) TF_R(6)   x0 += k1; x1 += k2 + 1u;
  TF_R(17) TF_R(29) TF_R(16) TF_R(24)  x0 += k2; x1 += k0 + 2u;
  TF_R(13) TF_R(15) TF_R(26) TF_R(6)   x0 += k0; x1 += k1 + 3u;
  TF_R(17) TF_R(29) TF_R(16) TF_R(24)  x0 += k1; x1 += k2 + 4u;
  TF_R(13) TF_R(15) TF_R(26) TF_R(6)   x0 += k2; x1 += k0 + 5u;
#undef TF_R
  return x0 ^ x1;
}

__global__ __launch_bounds__(128) void k_sample(
    const float* __restrict__ wsc, const float* __restrict__ bsc,
    float* __restrict__ out) {
  const int b = blockIdx.y;
  const int g = blockIdx.x * 128 + threadIdx.x;
  if (g >= NG) return;
  const int o = g / 25;
  const float4* pp = (const float4*)&g_pp[(b * NGB + o) * 16];
  const float4 pv0 = __ldg(pp + 0), pv1 = __ldg(pp + 1);
  const float4 lv0 = __ldg(pp + 2), lv1 = __ldg(pp + 3);
  const float p[NC]  = {pv0.x, pv0.y, pv0.z, pv0.w, pv1.x, pv1.y, pv1.z};
  const float lp[NC] = {lv0.x, lv0.y, lv0.z, lv0.w, lv1.x, lv1.y, lv1.z};
  const unsigned i0 = (unsigned)(b * NG + g) * 7u;

  float s[NC];
  float m = -3.0e38f;
#pragma unroll
  for (int c = 0; c < NC; c++) {
    const unsigned bits = tf_bits(i0 + (unsigned)c);
    const float u = __uint_as_float((bits >> 9) | 0x3f800000u) - 1.0f;
    const float gn = -__logf(-__logf(u + 1e-20f) + 1e-20f);
    const float sv = (lp[c] + gn) * 10.0f;  // /TEMP, TEMP=0.1
    s[c] = sv;
    m = fmaxf(m, sv);
  }
  float e[NC], sum = 0.0f;
#pragma unroll
  for (int c = 0; c < NC; c++) { e[c] = __expf(s[c] - m); sum += e[c]; }
  const float rinv = __fdividef(1.0f, sum);
  float y[NC], ym = 0.0f;
#pragma unroll
  for (int c = 0; c < NC; c++) { y[c] = e[c] * rinv; ym = fmaxf(ym, y[c]); }
  float smp = 0.0f;
#pragma unroll
  for (int c = 0; c < NC; c++) {
    const float yh = (y[c] == ym) ? 1.0f : 0.0f;
    smp += (float)c * ((yh - y[c]) + y[c]);   // straight-through forward value
  }
  const size_t bg = (size_t)b * NG + g;
  out[OFF_SAMPLE + bg] = smp;
  const float t = smp * wsc[g] + bsc[g];
  out[OFF_MU + bg] = __fdividef(1.0f, 1.0f + __expf(-t));
  float* po = out + OFF_PI + bg * 7;
#pragma unroll
  for (int c = 0; c < NC; c++) po[c] = p[c];
}

// ---------------------------------------------------------------------------
extern "C" void kernel_launch(void* const* d_in, const int* in_sizes, int n_in,
                              void* d_out, int out_size) {
  const float* z   = (const float*)d_in[0];
  const float* w0  = (const float*)d_in[1];
  const float* b0  = (const float*)d_in[2];
  const float* g0  = (const float*)d_in[3];
  const float* be0 = (const float*)d_in[4];
  const float* m0  = (const float*)d_in[5];
  const float* v0  = (const float*)d_in[6];
  const float* w1  = (const float*)d_in[7];
  const float* b1  = (const float*)d_in[8];
  const float* g1  = (const float*)d_in[9];
  const float* be1 = (const float*)d_in[10];
  const float* m1  = (const float*)d_in[11];
  const float* v1  = (const float*)d_in[12];
  const float* wr  = (const float*)d_in[13];
  const float* br  = (const float*)d_in[14];
  const float* wd  = (const float*)d_in[15];
  const float* bd  = (const float*)d_in[16];
  const float* wrho= (const float*)d_in[17];
  const float* brho= (const float*)d_in[18];
  const float* wsc = (const float*)d_in[19];
  const float* bsc = (const float*)d_in[20];
  float* out = (float*)d_out;

  // one-time side stream + fork/join events (created outside capture: the
  // harness runs kernel_launch once for correctness before capturing)
  static cudaStream_t s2 = nullptr;
  static cudaEvent_t evF = nullptr, evJ = nullptr;
  if (!s2) {
    cudaStreamCreateWithFlags(&s2, cudaStreamNonBlocking);
    cudaEventCreateWithFlags(&evF, cudaEventDisableTiming);
    cudaEventCreateWithFlags(&evJ, cudaEventDisableTiming);
  }

  k_mlp<<<NB, HID>>>(z, w0, b0, g0, be0, m0, v0, w1, b1, g1, be1, m1, v1);

  // fork: k_gemm on s2 runs concurrently with k_rho -> k_sample
  cudaEventRecord(evF, 0);
  cudaStreamWaitEvent(s2, evF, 0);
  dim3 gg((NG + BN - 1) / BN, NB / BM);
  k_gemm<<<gg, 256, 0, s2>>>(wr, br, wd, bd, out);
  cudaEventRecord(evJ, s2);

  k_rho<<<NGB / 8, 256>>>(wrho, brho);
  dim3 gs((NG + 127) / 128, NB);
  k_sample<<<gs, 128>>>(wsc, bsc, out);

  // join
  cudaStreamWaitEvent(0, evJ, 0);
}